// round 5
// baseline (speedup 1.0000x reference)
#include <cuda_runtime.h>

#define BATCH 2048
#define CELL 512
#define KDIM 30
#define LPAD 1024
#define VDIM 80

// scratch: [B, 90] = alpha | beta | kappa (kappa pre-summed with kappa_old)
__device__ float g_params[BATCH * 3 * KDIM];

// ---------------------------------------------------------------------------
// Kernel A: params = exp(x @ W.T + b).  16 batches per block (grid=128), so W
// is read from L2 only 128 times.  Warp-per-output, 16 smem accumulators.
// ---------------------------------------------------------------------------
__global__ __launch_bounds__(256) void params_kernel(
    const float* __restrict__ x,          // [B, CELL]
    const float* __restrict__ kappa_old,  // [B, K]
    const float* __restrict__ W,          // [3K, CELL]
    const float* __restrict__ bias,       // [3K]
    float* __restrict__ out_kappa)        // [B, K]
{
    __shared__ float4 xs[16 * CELL / 4];  // 32 KB

    const int tid = threadIdx.x;
    const int wid = tid >> 5;
    const int lane = tid & 31;
    const int b0 = blockIdx.x * 16;

    const float4* xg = (const float4*)(x + (size_t)b0 * CELL);
    #pragma unroll
    for (int i = tid; i < 16 * CELL / 4; i += 256)
        xs[i] = xg[i];
    __syncthreads();

    for (int o = wid; o < 3 * KDIM; o += 8) {
        const float4* wrow = (const float4*)(W + (size_t)o * CELL);
        float a[16];
        #pragma unroll
        for (int r = 0; r < 16; r++) a[r] = 0.0f;

        #pragma unroll
        for (int j = 0; j < 4; j++) {
            float4 w4 = wrow[lane + 32 * j];
            #pragma unroll
            for (int r = 0; r < 16; r++) {
                float4 v = xs[r * 128 + lane + 32 * j];
                a[r] = fmaf(w4.x, v.x,
                       fmaf(w4.y, v.y,
                       fmaf(w4.z, v.z,
                       fmaf(w4.w, v.w, a[r]))));
            }
        }
        #pragma unroll
        for (int off = 16; off; off >>= 1) {
            #pragma unroll
            for (int r = 0; r < 16; r++)
                a[r] += __shfl_xor_sync(0xffffffffu, a[r], off);
        }
        if (lane < 16) {
            float acc = a[lane];
            int b = b0 + lane;
            float p = __expf(acc + bias[o]);
            if (o >= 2 * KDIM) {
                int k = o - 2 * KDIM;
                p += kappa_old[(size_t)b * KDIM + k];
                out_kappa[(size_t)b * KDIM + k] = p;
            }
            g_params[(size_t)b * (3 * KDIM) + o] = p;
        }
    }
}

// ---------------------------------------------------------------------------
// Kernel B: sparse phi.  One block per batch; each Gaussian only touched
// where beta*(kappa-l)^2 < 92 (beyond that expf underflows -> contribution 0,
// identical to the fp32 reference within tolerance).
// ---------------------------------------------------------------------------
__global__ __launch_bounds__(256) void phi_kernel(
    const float* __restrict__ text_lens,  // [B, 1]
    float* __restrict__ out_phi)          // [B, L+1]
{
    __shared__ float s_par[3 * KDIM];
    __shared__ float s_phi[LPAD + 1];

    const int bid = blockIdx.x;
    const int tid = threadIdx.x;
    const int wid = tid >> 5;
    const int lane = tid & 31;

    if (tid < 3 * KDIM)
        s_par[tid] = g_params[(size_t)bid * (3 * KDIM) + tid];
    #pragma unroll
    for (int l = tid; l <= LPAD; l += 256)
        s_phi[l] = 0.0f;
    __syncthreads();

    for (int k = wid; k < KDIM; k += 8) {
        const float alpha = s_par[k];
        const float beta  = s_par[KDIM + k];
        const float kap   = s_par[2 * KDIM + k];
        const float r = fminf(sqrtf(92.0f / beta), 1100.0f);
        const int lo = max(0, (int)(kap - r));
        const int hi = min(LPAD, (int)(kap + r) + 1);
        for (int l = lo + lane; l <= hi; l += 32) {
            float d = kap - (float)l;
            atomicAdd(&s_phi[l], alpha * __expf(-beta * d * d));
        }
    }
    __syncthreads();

    const float scale = (float)LPAD / text_lens[bid];
    for (int l = tid; l <= LPAD; l += 256)
        out_phi[(size_t)bid * (LPAD + 1) + l] = s_phi[l] * scale;
}

// ---------------------------------------------------------------------------
// Kernel C: persistent streaming w reduction.  grid = 148*6 blocks,
// grid-stride over batches.  Branchless float4 stream + shared atomics.
// ---------------------------------------------------------------------------
__global__ __launch_bounds__(256, 6) void wsum_kernel(
    const float4* __restrict__ onehots,   // [B, L*V/4]
    const float* __restrict__ phi,        // [B, L+1]
    float* __restrict__ out_w)            // [B, V]
{
    __shared__ float s_phi[LPAD];
    __shared__ float s_w[VDIM];

    const int tid = threadIdx.x;

    // per-thread invariant geometry: float4 index tid + 256j; column base
    // has period 5 in j, row l advances +64 per 5-group.
    int l0[5], cb[5];
    #pragma unroll
    for (int m = 0; m < 5; m++) {
        int e0 = 4 * tid + 1024 * m;
        l0[m] = e0 / VDIM;
        cb[m] = e0 % VDIM;
    }

    for (int bid = blockIdx.x; bid < BATCH; bid += gridDim.x) {
        #pragma unroll
        for (int i = tid; i < LPAD; i += 256)
            s_phi[i] = phi[(size_t)bid * (LPAD + 1) + i];
        if (tid < VDIM) s_w[tid] = 0.0f;
        __syncthreads();

        const float4* oh = onehots + (size_t)bid * (LPAD * VDIM / 4);

        float4 acc[5];
        #pragma unroll
        for (int m = 0; m < 5; m++)
            acc[m] = make_float4(0.f, 0.f, 0.f, 0.f);

        #pragma unroll 2
        for (int g = 0; g < 16; g++) {
            #pragma unroll
            for (int m = 0; m < 5; m++) {
                float4 v4 = __ldcs(&oh[tid + 256 * (m + 5 * g)]);
                float ph = s_phi[l0[m] + 64 * g];
                acc[m].x = fmaf(ph, v4.x, acc[m].x);
                acc[m].y = fmaf(ph, v4.y, acc[m].y);
                acc[m].z = fmaf(ph, v4.z, acc[m].z);
                acc[m].w = fmaf(ph, v4.w, acc[m].w);
            }
        }
        __syncthreads();

        #pragma unroll
        for (int m = 0; m < 5; m++) {
            atomicAdd(&s_w[cb[m] + 0], acc[m].x);
            atomicAdd(&s_w[cb[m] + 1], acc[m].y);
            atomicAdd(&s_w[cb[m] + 2], acc[m].z);
            atomicAdd(&s_w[cb[m] + 3], acc[m].w);
        }
        __syncthreads();

        if (tid < VDIM) out_w[(size_t)bid * VDIM + tid] = s_w[tid];
        __syncthreads();
    }
}

extern "C" void kernel_launch(void* const* d_in, const int* in_sizes, int n_in,
                              void* d_out, int out_size) {
    const float* x         = (const float*)d_in[0];
    const float* kappa_old = (const float*)d_in[1];
    const float4* onehots  = (const float4*)d_in[2];
    const float* text_lens = (const float*)d_in[3];
    const float* W         = (const float*)d_in[4];
    const float* bias      = (const float*)d_in[5];

    float* out = (float*)d_out;
    float* out_w     = out;                                  // [B, V]
    float* out_kappa = out + (size_t)BATCH * VDIM;           // [B, K]
    float* out_phi   = out + (size_t)BATCH * (VDIM + KDIM);  // [B, L+1]

    params_kernel<<<BATCH / 16, 256>>>(x, kappa_old, W, bias, out_kappa);
    phi_kernel<<<BATCH, 256>>>(text_lens, out_phi);
    wsum_kernel<<<148 * 6, 256>>>(onehots, out_phi, out_w);
}